// round 5
// baseline (speedup 1.0000x reference)
#include <cuda_runtime.h>

// Problem constants
#define B_      32
#define C_      512
#define HW_     4096            // 64*64
#define NPIX    (B_ * HW_)      // 131072
#define M_      1024
#define THRESH  0.8f

// GEMM tiling
#define PX  64                  // pixels per block
#define MT  64                  // memory rows per m-tile
#define KC  32                  // K chunk
#define PAD 68                  // smem row pad (float4-aligned)

// Scratch (no cudaMalloc allowed)
__device__ float g_memn[M_ * C_];     // normalized memory, fp32
__device__ float g_pnorm2[NPIX];      // per-pixel ||x||^2
__device__ int   g_sel[NPIX];         // selected memory row or -1

// ---------------------------------------------------------------------------
// Kernel 0: normalize memory rows (1024 rows x 512)
// ---------------------------------------------------------------------------
__global__ void norm_mem_kernel(const float* __restrict__ mem) {
    int row = blockIdx.x;
    int t   = threadIdx.x;   // 128 threads, 4 floats each
    const float4* r = (const float4*)(mem + (size_t)row * C_);
    float4 v = r[t];
    float ss = v.x * v.x + v.y * v.y + v.z * v.z + v.w * v.w;
#pragma unroll
    for (int o = 16; o; o >>= 1) ss += __shfl_xor_sync(0xffffffffu, ss, o);
    __shared__ float ws[4];
    if ((t & 31) == 0) ws[t >> 5] = ss;
    __syncthreads();
    float tot = ws[0] + ws[1] + ws[2] + ws[3];
    float inv = 1.0f / fmaxf(sqrtf(tot), 1e-12f);
    float4 o4 = make_float4(v.x * inv, v.y * inv, v.z * inv, v.w * inv);
    ((float4*)(g_memn + (size_t)row * C_))[t] = o4;
}

// ---------------------------------------------------------------------------
// Kernel 1: per-pixel ||x||^2  (coalesced across hw within a warp)
// ---------------------------------------------------------------------------
__global__ void pix_norm_kernel(const float* __restrict__ x) {
    int p  = blockIdx.x * blockDim.x + threadIdx.x;  // pixel id
    int b  = p / HW_;
    int hw = p % HW_;
    const float* xb = x + (size_t)b * C_ * HW_ + hw;
    float s = 0.f;
#pragma unroll 8
    for (int c = 0; c < C_; c++) {
        float v = xb[(size_t)c * HW_];
        s += v * v;
    }
    g_pnorm2[p] = s;
}

// ---------------------------------------------------------------------------
// Kernel 2: fused GEMM (x . mem_norm^T) + running argmax per pixel.
// Block = 64 pixels; loops 16 m-tiles of 64; K in chunks of 32 via smem.
// Thread layout: tx = t&15 -> 4 m columns, ty = t>>4 -> 4 pixels.
// ---------------------------------------------------------------------------
__global__ __launch_bounds__(256, 4) void sim_kernel(const float* __restrict__ x) {
    __shared__ float xs[KC][PAD];        // [k][pixel]
    __shared__ float ms[KC][PAD];        // [k][m]
    __shared__ float redv[PX][17];
    __shared__ int   redi[PX][17];

    int t  = threadIdx.x;
    int tx = t & 15;
    int ty = t >> 4;
    int pix0 = blockIdx.x * PX;          // 64 consecutive pixels, single b
    int b    = pix0 / HW_;
    int hw0  = pix0 % HW_;
    const float* xb = x + (size_t)b * C_ * HW_ + hw0;

    float bestv[4] = {-1e30f, -1e30f, -1e30f, -1e30f};
    int   besti[4] = {0, 0, 0, 0};

    for (int mt = 0; mt < M_ / MT; mt++) {
        float acc[4][4];
#pragma unroll
        for (int i = 0; i < 4; i++)
#pragma unroll
            for (int j = 0; j < 4; j++) acc[i][j] = 0.f;

        for (int kc0 = 0; kc0 < C_; kc0 += KC) {
            __syncthreads();
            // load x chunk: xs[c][px], coalesced over px
            {
                int px = t & 63;
                int cc = t >> 6;             // 0..3
#pragma unroll
                for (int p = 0; p < 8; p++) {
                    int c = cc + p * 4;      // 0..31
                    xs[c][px] = xb[(size_t)(kc0 + c) * HW_ + px];
                }
            }
            // load mem chunk transposed: ms[c][m], coalesced over c
            {
                int j = t & 31;              // c offset
                int i = t >> 5;              // 0..7
#pragma unroll
                for (int p = 0; p < 8; p++) {
                    int mm = i + p * 8;      // 0..63
                    ms[j][mm] = g_memn[(size_t)(mt * MT + mm) * C_ + kc0 + j];
                }
            }
            __syncthreads();

#pragma unroll 8
            for (int k = 0; k < KC; k++) {
                float4 a4 = *(const float4*)&xs[k][ty * 4];
                float4 b4 = *(const float4*)&ms[k][tx * 4];
                float av[4] = {a4.x, a4.y, a4.z, a4.w};
                float bv[4] = {b4.x, b4.y, b4.z, b4.w};
#pragma unroll
                for (int i = 0; i < 4; i++)
#pragma unroll
                    for (int j = 0; j < 4; j++)
                        acc[i][j] = fmaf(av[i], bv[j], acc[i][j]);
            }
        }

        // fold this m-tile into running argmax
#pragma unroll
        for (int j = 0; j < 4; j++) {
            int m = mt * MT + tx * 4 + j;
#pragma unroll
            for (int i = 0; i < 4; i++) {
                if (acc[i][j] > bestv[i]) { bestv[i] = acc[i][j]; besti[i] = m; }
            }
        }
    }

    // cross-thread (tx) reduction per pixel
    __syncthreads();
#pragma unroll
    for (int i = 0; i < 4; i++) {
        redv[ty * 4 + i][tx] = bestv[i];
        redi[ty * 4 + i][tx] = besti[i];
    }
    __syncthreads();
    if (t < PX) {
        float bv = -1e30f; int bi = 0;
#pragma unroll
        for (int j = 0; j < 16; j++) {
            float v = redv[t][j];
            if (v > bv) { bv = v; bi = redi[t][j]; }
        }
        float n2 = g_pnorm2[pix0 + t];
        // sim > 0.8  <=>  dot > 0.8 * ||x||
        int sel = (bv > THRESH * sqrtf(n2)) ? bi : -1;
        g_sel[pix0 + t] = sel;
    }
}

// ---------------------------------------------------------------------------
// Kernel 3: masked gather + channel-major scatter. float4 over hw.
// ---------------------------------------------------------------------------
__global__ void out_kernel(const float* __restrict__ mem, float* __restrict__ out) {
    int e4 = blockIdx.x * blockDim.x + threadIdx.x;   // float4 index
    int e  = e4 * 4;
    int hw = e & (HW_ - 1);
    int c  = (e >> 12) & (C_ - 1);
    int b  = e >> 21;                                  // e / (HW_*C_)
    int p  = b * HW_ + hw;
    int s0 = g_sel[p + 0];
    int s1 = g_sel[p + 1];
    int s2 = g_sel[p + 2];
    int s3 = g_sel[p + 3];
    float4 o;
    o.x = (s0 >= 0) ? mem[(size_t)s0 * C_ + c] : 0.f;
    o.y = (s1 >= 0) ? mem[(size_t)s1 * C_ + c] : 0.f;
    o.z = (s2 >= 0) ? mem[(size_t)s2 * C_ + c] : 0.f;
    o.w = (s3 >= 0) ? mem[(size_t)s3 * C_ + c] : 0.f;
    ((float4*)out)[e4] = o;
}

// ---------------------------------------------------------------------------
extern "C" void kernel_launch(void* const* d_in, const int* in_sizes, int n_in,
                              void* d_out, int out_size) {
    const float* x   = (const float*)d_in[0];   // 32*512*64*64
    const float* mem = (const float*)d_in[1];   // 1024*512
    float* out = (float*)d_out;

    norm_mem_kernel<<<M_, 128>>>(mem);
    pix_norm_kernel<<<NPIX / 256, 256>>>(x);
    sim_kernel<<<NPIX / PX, 256>>>(x);
    out_kernel<<<(NPIX * C_ / 4) / 256, 256>>>(mem, out);
}

// round 7
// speedup vs baseline: 5.3904x; 5.3904x over previous
#include <cuda_runtime.h>
#include <cuda_bf16.h>
#include <cstdint>

// Problem constants
#define B_      32
#define C_      512
#define HW_     4096            // 64*64
#define NPIX    (B_ * HW_)      // 131072
#define M_      1024
#define THRESH  0.8f

// ---------------------------------------------------------------------------
// Device scratch (no cudaMalloc allowed)
// ---------------------------------------------------------------------------
__device__ __nv_bfloat16 g_memn_bf[M_ * C_];             // normalized memory, bf16
__device__ __nv_bfloat16 g_xbf[(size_t)NPIX * C_];       // x transposed to [pix][K], bf16
__device__ float g_pnorm2[NPIX];                         // per-pixel ||x||^2 (fp32 exact)
__device__ int   g_sel[NPIX];                            // selected memory row or -1

__device__ __forceinline__ uint32_t smem_u32(const void* p) {
    uint32_t a;
    asm("{ .reg .u64 t; cvta.to.shared.u64 t, %1; cvt.u32.u64 %0, t; }" : "=r"(a) : "l"(p));
    return a;
}

__device__ __forceinline__ void ldsm_x4(uint32_t* r, uint32_t addr) {
    asm volatile("ldmatrix.sync.aligned.m8n8.x4.shared.b16 {%0,%1,%2,%3}, [%4];"
        : "=r"(r[0]), "=r"(r[1]), "=r"(r[2]), "=r"(r[3]) : "r"(addr));
}

__device__ __forceinline__ void mma_bf16(float* d, const uint32_t* a, const uint32_t* b) {
    asm volatile("mma.sync.aligned.m16n8k16.row.col.f32.bf16.bf16.f32 "
        "{%0,%1,%2,%3}, {%4,%5,%6,%7}, {%8,%9}, {%0,%1,%2,%3};"
        : "+f"(d[0]), "+f"(d[1]), "+f"(d[2]), "+f"(d[3])
        : "r"(a[0]), "r"(a[1]), "r"(a[2]), "r"(a[3]), "r"(b[0]), "r"(b[1]));
}

// ---------------------------------------------------------------------------
// Kernel 0: normalize memory rows -> bf16
// ---------------------------------------------------------------------------
__global__ void norm_mem_kernel(const float* __restrict__ mem) {
    int row = blockIdx.x;
    int t   = threadIdx.x;   // 128 threads, 4 floats each
    const float4* r = (const float4*)(mem + (size_t)row * C_);
    float4 v = r[t];
    float ss = v.x * v.x + v.y * v.y + v.z * v.z + v.w * v.w;
#pragma unroll
    for (int o = 16; o; o >>= 1) ss += __shfl_xor_sync(0xffffffffu, ss, o);
    __shared__ float ws[4];
    if ((t & 31) == 0) ws[t >> 5] = ss;
    __syncthreads();
    float tot = ws[0] + ws[1] + ws[2] + ws[3];
    float inv = 1.0f / fmaxf(sqrtf(tot), 1e-12f);
    __nv_bfloat162 p0 = __floats2bfloat162_rn(v.x * inv, v.y * inv);
    __nv_bfloat162 p1 = __floats2bfloat162_rn(v.z * inv, v.w * inv);
    uint2 o2;
    o2.x = *(uint32_t*)&p0;
    o2.y = *(uint32_t*)&p1;
    ((uint2*)(g_memn_bf + (size_t)row * C_))[t] = o2;
}

// ---------------------------------------------------------------------------
// Kernel 1: per-pixel ||x||^2 (fp32 exact, coalesced over hw)
// ---------------------------------------------------------------------------
__global__ void pix_norm_kernel(const float* __restrict__ x) {
    int p  = blockIdx.x * blockDim.x + threadIdx.x;
    int b  = p / HW_;
    int hw = p % HW_;
    const float* xb = x + (size_t)b * C_ * HW_ + hw;
    float s = 0.f;
#pragma unroll 8
    for (int c = 0; c < C_; c++) {
        float v = xb[(size_t)c * HW_];
        s += v * v;
    }
    g_pnorm2[p] = s;
}

// ---------------------------------------------------------------------------
// Kernel 2: transpose + convert x [B][C][HW] fp32 -> g_xbf [pix][C] bf16
// ---------------------------------------------------------------------------
__global__ __launch_bounds__(256) void xpose_kernel(const float* __restrict__ x) {
    __shared__ float xs[64][65];
    int bid = blockIdx.x;
    int ht = bid & 63;            // hw tile (64 tiles of 64)
    int ct = (bid >> 6) & 7;      // c tile (8 tiles of 64)
    int b  = bid >> 9;            // batch
    const float* src = x + ((size_t)b * C_ + ct * 64) * HW_ + ht * 64;
    int t  = threadIdx.x;
    int hw = t & 63;
    int cl = t >> 6;              // 0..3
#pragma unroll
    for (int i = 0; i < 16; i++) {
        xs[cl + i * 4][hw] = src[(size_t)(cl + i * 4) * HW_ + hw];
    }
    __syncthreads();
    int px = t >> 2;              // 0..63 (pixel within tile)
    int ch = (t & 3) * 16;        // 16-c chunk
    __nv_bfloat162 v[8];
#pragma unroll
    for (int j = 0; j < 8; j++) {
        v[j] = __floats2bfloat162_rn(xs[ch + j * 2][px], xs[ch + j * 2 + 1][px]);
    }
    size_t p = (size_t)b * HW_ + ht * 64 + px;
    uint4* dst = (uint4*)(g_xbf + p * C_ + ct * 64 + ch);
    dst[0] = *(uint4*)&v[0];
    dst[1] = *(uint4*)&v[4];
}

// ---------------------------------------------------------------------------
// Kernel 3: bf16 HMMA (mma.sync m16n8k16) GEMM + fused argmax.
// CTA = 256 threads (8 warps) = 128 pixels.
// A (128px x 512K bf16) SMEM-resident, pitch 520 bf16 (1040 B) -> conflict-free
// ldmatrix. Loop 8 N-tiles of 128 memory rows; B streamed in 64-K chunks,
// double-buffered (pitch 72 bf16 = 144 B).
// Warp grid 2x4: warp tile 64px x 32m = 4x4 mma tiles. Argmax fused in regs.
// ---------------------------------------------------------------------------
#define A_PITCH_B  1040          // 520 bf16
#define B_PITCH_B  144           // 72 bf16
#define OFF_B      133120        // 128 * 1040
#define B_CHUNK    18432         // 128 * 144
#define OFF_REDV   169984        // OFF_B + 2*B_CHUNK
#define OFF_REDI   172032
#define SMEM_BYTES 174080

__global__ __launch_bounds__(256, 1) void sim_mma_kernel() {
    extern __shared__ char smem[];
    uint32_t sb = smem_u32(smem);
    float* redv = (float*)(smem + OFF_REDV);   // [128][4]
    int*   redi = (int*)(smem + OFF_REDI);     // [128][4]

    int t    = threadIdx.x;
    int lane = t & 31;
    int w    = t >> 5;
    int wr   = w & 1;      // pixel half (64 px)
    int wc   = w >> 1;     // m quarter (32 m)
    int pix0 = blockIdx.x * 128;

    // ---- load A resident: g_xbf rows pix0..pix0+127 -> pitch-520 layout ----
    {
        const uint4* asrc = (const uint4*)(g_xbf + (size_t)pix0 * C_);
#pragma unroll
        for (int i = 0; i < 32; i++) {
            int idx = t + i * 256;           // 0..8191 (16B quads; 64 per row)
            uint4 v = asrc[idx];
            int px = idx >> 6;
            int q  = idx & 63;
            *(uint4*)(smem + px * A_PITCH_B + q * 16) = v;
        }
    }

    // ---- hoisted ldmatrix base addresses ----
    uint32_t aAddr[4];
#pragma unroll
    for (int i = 0; i < 4; i++)
        aAddr[i] = sb + (uint32_t)(wr * 64 + i * 16 + (lane & 15)) * A_PITCH_B
                      + (uint32_t)(lane >> 4) * 16u;
    uint32_t bAddr[2];
#pragma unroll
    for (int jp = 0; jp < 2; jp++)
        bAddr[jp] = sb + OFF_B
                  + (uint32_t)(wc * 32 + (2 * jp + (lane >> 4)) * 8 + (lane & 7)) * B_PITCH_B
                  + (uint32_t)((lane >> 3) & 1) * 16u;

    float bestv[4][2];
    int   besti[4][2];
#pragma unroll
    for (int i = 0; i < 4; i++) {
        bestv[i][0] = -1e30f; bestv[i][1] = -1e30f;
        besti[i][0] = 0;      besti[i][1] = 0;
    }

    // B chunk loader: rows nt*128..+127, k cols kc*64..+63
    auto loadB = [&](int nt, int kc, int buf) {
        const uint4* bsrc = (const uint4*)(g_memn_bf + (size_t)(nt * 128) * C_ + kc * 64);
#pragma unroll
        for (int i = 0; i < 4; i++) {
            int idx = t + i * 256;           // 0..1023 quads (8 per row)
            int m = idx >> 3;
            int q = idx & 7;
            uint4 v = bsrc[(size_t)m * 64 + q];
            *(uint4*)(smem + OFF_B + buf * B_CHUNK + m * B_PITCH_B + q * 16) = v;
        }
    };

    loadB(0, 0, 0);   // prologue

    for (int nt = 0; nt < 8; nt++) {
        float acc[4][4][4];
#pragma unroll
        for (int i = 0; i < 4; i++)
#pragma unroll
            for (int j = 0; j < 4; j++)
#pragma unroll
                for (int r = 0; r < 4; r++) acc[i][j][r] = 0.f;

        for (int kc = 0; kc < 8; kc++) {
            __syncthreads();   // buf kc&1 ready; prev compute done on buf (kc+1)&1
            // issue next chunk load into other buffer
            {
                int nkc = kc + 1, nnt = nt;
                if (nkc == 8) { nkc = 0; nnt = nt + 1; }
                if (nnt < 8) loadB(nnt, nkc, (kc + 1) & 1);
            }
            uint32_t bufOff = (uint32_t)((kc & 1) * B_CHUNK);
            uint32_t kcOff  = (uint32_t)(kc * 128);   // kc*64 bf16 cols in A
#pragma unroll
            for (int ks = 0; ks < 4; ks++) {
                uint32_t ko = (uint32_t)(ks * 32);    // 16 bf16 cols
                uint32_t af[4][4];
#pragma unroll
                for (int i = 0; i < 4; i++)
                    ldsm_x4(af[i], aAddr[i] + kcOff + ko);
                uint32_t bfr[2][4];
#pragma unroll
                for (int jp = 0; jp < 2; jp++)
                    ldsm_x4(bfr[jp], bAddr[jp] + bufOff + ko);
#pragma unroll
                for (int i = 0; i < 4; i++)
#pragma unroll
                    for (int j = 0; j < 4; j++)
                        mma_bf16(acc[i][j], af[i], &bfr[j >> 1][(j & 1) * 2]);
            }
        }

        // ---- fold this N-tile into running argmax (first-max tie-break) ----
#pragma unroll
        for (int i = 0; i < 4; i++)
#pragma unroll
            for (int rp = 0; rp < 2; rp++)
#pragma unroll
                for (int j = 0; j < 4; j++)
#pragma unroll
                    for (int c = 0; c < 2; c++) {
                        float v = acc[i][j][rp * 2 + c];
                        if (v > bestv[i][rp]) {
                            bestv[i][rp] = v;
                            besti[i][rp] = nt * 128 + wc * 32 + j * 8 + (lane & 3) * 2 + c;
                        }
                    }
    }

    // ---- quad reduction (cols within warp) + cross-warp smem reduction ----
#pragma unroll
    for (int i = 0; i < 4; i++)
#pragma unroll
        for (int rp = 0; rp < 2; rp++) {
            float v = bestv[i][rp];
            int   ix = besti[i][rp];
#pragma unroll
            for (int off = 1; off <= 2; off <<= 1) {
                float ov = __shfl_xor_sync(0xffffffffu, v, off);
                int   oi = __shfl_xor_sync(0xffffffffu, ix, off);
                if (ov > v || (ov == v && oi < ix)) { v = ov; ix = oi; }
            }
            if ((lane & 3) == 0) {
                int row = wr * 64 + i * 16 + (lane >> 2) + rp * 8;
                redv[row * 4 + wc] = v;
                redi[row * 4 + wc] = ix;
            }
        }
    __syncthreads();
    if (t < 128) {
        float bv = redv[t * 4];
        int   bi = redi[t * 4];
#pragma unroll
        for (int j = 1; j < 4; j++) {
            float v = redv[t * 4 + j];
            if (v > bv) { bv = v; bi = redi[t * 4 + j]; }
        }
        float n2 = g_pnorm2[pix0 + t];
        g_sel[pix0 + t] = (bv > THRESH * sqrtf(n2)) ? bi : -1;
    }
}

// ---------------------------------------------------------------------------
// Kernel 4: masked gather + channel-major scatter. float4 over hw.
// ---------------------------------------------------------------------------
__global__ void out_kernel(const float* __restrict__ mem, float* __restrict__ out) {
    int e4 = blockIdx.x * blockDim.x + threadIdx.x;
    int e  = e4 * 4;
    int hw = e & (HW_ - 1);
    int c  = (e >> 12) & (C_ - 1);
    int b  = e >> 21;
    int p  = b * HW_ + hw;
    int s0 = g_sel[p + 0];
    int s1 = g_sel[p + 1];
    int s2 = g_sel[p + 2];
    int s3 = g_sel[p + 3];
    float4 o;
    o.x = (s0 >= 0) ? mem[(size_t)s0 * C_ + c] : 0.f;
    o.y = (s1 >= 0) ? mem[(size_t)s1 * C_ + c] : 0.f;
    o.z = (s2 >= 0) ? mem[(size_t)s2 * C_ + c] : 0.f;
    o.w = (s3 >= 0) ? mem[(size_t)s3 * C_ + c] : 0.f;
    ((float4*)out)[e4] = o;
}

// ---------------------------------------------------------------------------
extern "C" void kernel_launch(void* const* d_in, const int* in_sizes, int n_in,
                              void* d_out, int out_size) {
    const float* x   = (const float*)d_in[0];   // 32*512*64*64
    const float* mem = (const float*)d_in[1];   // 1024*512
    float* out = (float*)d_out;

    cudaFuncSetAttribute(sim_mma_kernel,
                         cudaFuncAttributeMaxDynamicSharedMemorySize, SMEM_BYTES);

    norm_mem_kernel<<<M_, 128>>>(mem);
    pix_norm_kernel<<<NPIX / 256, 256>>>(x);
    xpose_kernel<<<B_ * 8 * 64, 256>>>(x);
    sim_mma_kernel<<<NPIX / 128, 256, SMEM_BYTES>>>();
    out_kernel<<<(NPIX * C_ / 4) / 256, 256>>>(mem, out);
}

// round 8
// speedup vs baseline: 6.1927x; 1.1488x over previous
#include <cuda_runtime.h>
#include <cuda_bf16.h>
#include <cstdint>

// Problem constants
#define B_      32
#define C_      512
#define HW_     4096            // 64*64
#define NPIX    (B_ * HW_)      // 131072
#define M_      1024
#define THRESH  0.8f

// ---------------------------------------------------------------------------
// Device scratch (no cudaMalloc allowed)
// ---------------------------------------------------------------------------
__device__ __nv_bfloat16 g_memn_bf[M_ * C_];             // normalized memory, bf16
__device__ __nv_bfloat16 g_xbf[(size_t)NPIX * C_];       // x transposed to [pix][K], bf16
__device__ float g_pnorm2[NPIX];                         // per-pixel ||x||^2 (fp32 exact)
__device__ int   g_sel[NPIX];                            // selected memory row or -1

__device__ __forceinline__ uint32_t smem_u32(const void* p) {
    uint32_t a;
    asm("{ .reg .u64 t; cvta.to.shared.u64 t, %1; cvt.u32.u64 %0, t; }" : "=r"(a) : "l"(p));
    return a;
}

__device__ __forceinline__ void ldsm_x4(uint32_t* r, uint32_t addr) {
    asm volatile("ldmatrix.sync.aligned.m8n8.x4.shared.b16 {%0,%1,%2,%3}, [%4];"
        : "=r"(r[0]), "=r"(r[1]), "=r"(r[2]), "=r"(r[3]) : "r"(addr));
}

__device__ __forceinline__ void mma_bf16(float* d, const uint32_t* a, const uint32_t* b) {
    asm volatile("mma.sync.aligned.m16n8k16.row.col.f32.bf16.bf16.f32 "
        "{%0,%1,%2,%3}, {%4,%5,%6,%7}, {%8,%9}, {%0,%1,%2,%3};"
        : "+f"(d[0]), "+f"(d[1]), "+f"(d[2]), "+f"(d[3])
        : "r"(a[0]), "r"(a[1]), "r"(a[2]), "r"(a[3]), "r"(b[0]), "r"(b[1]));
}

// ---------------------------------------------------------------------------
// Kernel 0: normalize memory rows -> bf16
// ---------------------------------------------------------------------------
__global__ void norm_mem_kernel(const float* __restrict__ mem) {
    int row = blockIdx.x;
    int t   = threadIdx.x;   // 128 threads, 4 floats each
    const float4* r = (const float4*)(mem + (size_t)row * C_);
    float4 v = r[t];
    float ss = v.x * v.x + v.y * v.y + v.z * v.z + v.w * v.w;
#pragma unroll
    for (int o = 16; o; o >>= 1) ss += __shfl_xor_sync(0xffffffffu, ss, o);
    __shared__ float ws[4];
    if ((t & 31) == 0) ws[t >> 5] = ss;
    __syncthreads();
    float tot = ws[0] + ws[1] + ws[2] + ws[3];
    float inv = 1.0f / fmaxf(sqrtf(tot), 1e-12f);
    __nv_bfloat162 p0 = __floats2bfloat162_rn(v.x * inv, v.y * inv);
    __nv_bfloat162 p1 = __floats2bfloat162_rn(v.z * inv, v.w * inv);
    uint2 o2;
    o2.x = *(uint32_t*)&p0;
    o2.y = *(uint32_t*)&p1;
    ((uint2*)(g_memn_bf + (size_t)row * C_))[t] = o2;
}

// ---------------------------------------------------------------------------
// Kernel 1: fused transpose+convert+norm.
// Block = 64 pixels (one hw tile) x ALL 512 channels, 256 threads.
// Accumulates exact fp32 ||x||^2 while transposing -> no separate norm pass.
// ---------------------------------------------------------------------------
__global__ __launch_bounds__(256) void xpose_norm_kernel(const float* __restrict__ x) {
    __shared__ float xs[64][65];
    int bid = blockIdx.x;
    int ht = bid & 63;            // hw tile (64 tiles of 64)
    int b  = bid >> 6;            // batch
    int t  = threadIdx.x;
    int hw = t & 63;
    int cl = t >> 6;              // 0..3
    int px = t >> 2;              // 0..63 (pixel within tile, write phase)
    int ch = (t & 3) * 16;        // 16-c chunk within 64-c tile

    float ss = 0.f;

    for (int ct = 0; ct < 8; ct++) {
        const float* src = x + ((size_t)b * C_ + ct * 64) * HW_ + ht * 64;
#pragma unroll
        for (int i = 0; i < 16; i++) {
            xs[cl + i * 4][hw] = src[(size_t)(cl + i * 4) * HW_ + hw];
        }
        __syncthreads();
        __nv_bfloat162 v[8];
#pragma unroll
        for (int j = 0; j < 8; j++) {
            float a = xs[ch + j * 2][px];
            float bb = xs[ch + j * 2 + 1][px];
            ss += a * a + bb * bb;
            v[j] = __floats2bfloat162_rn(a, bb);
        }
        size_t p = (size_t)b * HW_ + ht * 64 + px;
        uint4* dst = (uint4*)(g_xbf + p * C_ + ct * 64 + ch);
        dst[0] = *(uint4*)&v[0];
        dst[1] = *(uint4*)&v[4];
        __syncthreads();
    }

    // reduce ss across the 4 threads sharing a pixel (same quad in warp)
    ss += __shfl_xor_sync(0xffffffffu, ss, 1);
    ss += __shfl_xor_sync(0xffffffffu, ss, 2);
    if ((t & 3) == 0) {
        g_pnorm2[(size_t)b * HW_ + ht * 64 + px] = ss;
    }
}

// ---------------------------------------------------------------------------
// Kernel 2: bf16 HMMA (mma.sync m16n8k16) GEMM + fused argmax.
// CTA = 256 threads (8 warps) = 64 pixels; 2 CTAs/SM (smem ~103KB, regs<=128).
// A (64px x 512K bf16) SMEM-resident, pitch 520 bf16 (1040 B).
// Loop 8 N-tiles of 128 memory rows; B streamed in 64-K chunks, double-buffered.
// Warp grid 2x4: warp tile 32px x 32m = 2x4 mma tiles. Argmax fused in regs.
// ---------------------------------------------------------------------------
#define A_PITCH_B  1040          // 520 bf16
#define B_PITCH_B  144           // 72 bf16
#define OFF_B      66560         // 64 * 1040
#define B_CHUNK    18432         // 128 * 144
#define OFF_REDV   103424        // OFF_B + 2*B_CHUNK
#define OFF_REDI   104448
#define SMEM_BYTES 105472

__global__ __launch_bounds__(256, 2) void sim_mma_kernel() {
    extern __shared__ char smem[];
    uint32_t sb = smem_u32(smem);
    float* redv = (float*)(smem + OFF_REDV);   // [64][4]
    int*   redi = (int*)(smem + OFF_REDI);     // [64][4]

    int t    = threadIdx.x;
    int lane = t & 31;
    int w    = t >> 5;
    int wr   = w & 1;      // pixel half (32 px)
    int wc   = w >> 1;     // m quarter (32 m)
    int pix0 = blockIdx.x * 64;

    // ---- load A resident: g_xbf rows pix0..pix0+63 -> pitch-520 layout ----
    {
        const uint4* asrc = (const uint4*)(g_xbf + (size_t)pix0 * C_);
#pragma unroll
        for (int i = 0; i < 16; i++) {
            int idx = t + i * 256;           // 0..4095 (16B quads; 64 per row)
            uint4 v = asrc[idx];
            int px = idx >> 6;
            int q  = idx & 63;
            *(uint4*)(smem + px * A_PITCH_B + q * 16) = v;
        }
    }

    // ---- hoisted ldmatrix base addresses ----
    uint32_t aAddr[2];
#pragma unroll
    for (int i = 0; i < 2; i++)
        aAddr[i] = sb + (uint32_t)(wr * 32 + i * 16 + (lane & 15)) * A_PITCH_B
                      + (uint32_t)(lane >> 4) * 16u;
    uint32_t bAddr[2];
#pragma unroll
    for (int jp = 0; jp < 2; jp++)
        bAddr[jp] = sb + OFF_B
                  + (uint32_t)(wc * 32 + (2 * jp + (lane >> 4)) * 8 + (lane & 7)) * B_PITCH_B
                  + (uint32_t)((lane >> 3) & 1) * 16u;

    float bestv[2][2];
    int   besti[2][2];
#pragma unroll
    for (int i = 0; i < 2; i++) {
        bestv[i][0] = -1e30f; bestv[i][1] = -1e30f;
        besti[i][0] = 0;      besti[i][1] = 0;
    }

    // B chunk loader: rows nt*128..+127, k cols kc*64..+63
    auto loadB = [&](int nt, int kc, int buf) {
        const uint4* bsrc = (const uint4*)(g_memn_bf + (size_t)(nt * 128) * C_ + kc * 64);
#pragma unroll
        for (int i = 0; i < 4; i++) {
            int idx = t + i * 256;           // 0..1023 quads (8 per row)
            int m = idx >> 3;
            int q = idx & 7;
            uint4 v = bsrc[(size_t)m * 64 + q];
            *(uint4*)(smem + OFF_B + buf * B_CHUNK + m * B_PITCH_B + q * 16) = v;
        }
    };

    loadB(0, 0, 0);   // prologue

    for (int nt = 0; nt < 8; nt++) {
        float acc[2][4][4];
#pragma unroll
        for (int i = 0; i < 2; i++)
#pragma unroll
            for (int j = 0; j < 4; j++)
#pragma unroll
                for (int r = 0; r < 4; r++) acc[i][j][r] = 0.f;

        for (int kc = 0; kc < 8; kc++) {
            __syncthreads();   // buf kc&1 ready; prev compute done on buf (kc+1)&1
            // issue next chunk load into other buffer
            {
                int nkc = kc + 1, nnt = nt;
                if (nkc == 8) { nkc = 0; nnt = nt + 1; }
                if (nnt < 8) loadB(nnt, nkc, (kc + 1) & 1);
            }
            uint32_t bufOff = (uint32_t)((kc & 1) * B_CHUNK);
            uint32_t kcOff  = (uint32_t)(kc * 128);   // kc*64 bf16 cols in A
#pragma unroll
            for (int ks = 0; ks < 4; ks++) {
                uint32_t ko = (uint32_t)(ks * 32);    // 16 bf16 cols
                uint32_t af[2][4];
#pragma unroll
                for (int i = 0; i < 2; i++)
                    ldsm_x4(af[i], aAddr[i] + kcOff + ko);
                uint32_t bfr[2][4];
#pragma unroll
                for (int jp = 0; jp < 2; jp++)
                    ldsm_x4(bfr[jp], bAddr[jp] + bufOff + ko);
#pragma unroll
                for (int i = 0; i < 2; i++)
#pragma unroll
                    for (int j = 0; j < 4; j++)
                        mma_bf16(acc[i][j], af[i], &bfr[j >> 1][(j & 1) * 2]);
            }
        }

        // ---- fold this N-tile into running argmax (first-max tie-break) ----
#pragma unroll
        for (int i = 0; i < 2; i++)
#pragma unroll
            for (int rp = 0; rp < 2; rp++)
#pragma unroll
                for (int j = 0; j < 4; j++)
#pragma unroll
                    for (int c = 0; c < 2; c++) {
                        float v = acc[i][j][rp * 2 + c];
                        if (v > bestv[i][rp]) {
                            bestv[i][rp] = v;
                            besti[i][rp] = nt * 128 + wc * 32 + j * 8 + (lane & 3) * 2 + c;
                        }
                    }
    }

    // ---- quad reduction (cols within warp) + cross-warp smem reduction ----
#pragma unroll
    for (int i = 0; i < 2; i++)
#pragma unroll
        for (int rp = 0; rp < 2; rp++) {
            float v = bestv[i][rp];
            int   ix = besti[i][rp];
#pragma unroll
            for (int off = 1; off <= 2; off <<= 1) {
                float ov = __shfl_xor_sync(0xffffffffu, v, off);
                int   oi = __shfl_xor_sync(0xffffffffu, ix, off);
                if (ov > v || (ov == v && oi < ix)) { v = ov; ix = oi; }
            }
            if ((lane & 3) == 0) {
                int row = wr * 32 + i * 16 + (lane >> 2) + rp * 8;
                redv[row * 4 + wc] = v;
                redi[row * 4 + wc] = ix;
            }
        }
    __syncthreads();
    if (t < 64) {
        float bv = redv[t * 4];
        int   bi = redi[t * 4];
#pragma unroll
        for (int j = 1; j < 4; j++) {
            float v = redv[t * 4 + j];
            if (v > bv) { bv = v; bi = redi[t * 4 + j]; }
        }
        float n2 = g_pnorm2[pix0 + t];
        g_sel[pix0 + t] = (bv > THRESH * sqrtf(n2)) ? bi : -1;
    }
}

// ---------------------------------------------------------------------------
// Kernel 3: masked gather + channel-major scatter. float4 over hw.
// ---------------------------------------------------------------------------
__global__ void out_kernel(const float* __restrict__ mem, float* __restrict__ out) {
    int e4 = blockIdx.x * blockDim.x + threadIdx.x;
    int e  = e4 * 4;
    int hw = e & (HW_ - 1);
    int c  = (e >> 12) & (C_ - 1);
    int b  = e >> 21;
    int p  = b * HW_ + hw;
    int s0 = g_sel[p + 0];
    int s1 = g_sel[p + 1];
    int s2 = g_sel[p + 2];
    int s3 = g_sel[p + 3];
    float4 o;
    o.x = (s0 >= 0) ? mem[(size_t)s0 * C_ + c] : 0.f;
    o.y = (s1 >= 0) ? mem[(size_t)s1 * C_ + c] : 0.f;
    o.z = (s2 >= 0) ? mem[(size_t)s2 * C_ + c] : 0.f;
    o.w = (s3 >= 0) ? mem[(size_t)s3 * C_ + c] : 0.f;
    ((float4*)out)[e4] = o;
}

// ---------------------------------------------------------------------------
extern "C" void kernel_launch(void* const* d_in, const int* in_sizes, int n_in,
                              void* d_out, int out_size) {
    const float* x   = (const float*)d_in[0];   // 32*512*64*64
    const float* mem = (const float*)d_in[1];   // 1024*512
    float* out = (float*)d_out;

    cudaFuncSetAttribute(sim_mma_kernel,
                         cudaFuncAttributeMaxDynamicSharedMemorySize, SMEM_BYTES);

    norm_mem_kernel<<<M_, 128>>>(mem);
    xpose_norm_kernel<<<B_ * 64, 256>>>(x);
    sim_mma_kernel<<<NPIX / 64, 256, SMEM_BYTES>>>();
    out_kernel<<<(NPIX * C_ / 4) / 256, 256>>>(mem, out);
}

// round 9
// speedup vs baseline: 6.9911x; 1.1289x over previous
#include <cuda_runtime.h>
#include <cuda_bf16.h>
#include <cstdint>

// Problem constants
#define B_      32
#define C_      512
#define HW_     4096            // 64*64
#define NPIX    (B_ * HW_)      // 131072
#define M_      1024
#define THRESH  0.8f

// ---------------------------------------------------------------------------
// Device scratch (no cudaMalloc allowed)
// ---------------------------------------------------------------------------
__device__ __nv_bfloat16 g_memn_bf[M_ * C_];             // normalized memory, bf16
__device__ __nv_bfloat16 g_xbf[(size_t)NPIX * C_];       // x transposed to [pix][K], bf16
__device__ float g_pnorm2[NPIX];                         // per-pixel ||x||^2 (fp32 exact)
__device__ int   g_sel[NPIX];                            // selected memory row or -1

__device__ __forceinline__ uint32_t smem_u32(const void* p) {
    uint32_t a;
    asm("{ .reg .u64 t; cvta.to.shared.u64 t, %1; cvt.u32.u64 %0, t; }" : "=r"(a) : "l"(p));
    return a;
}

__device__ __forceinline__ void ldsm_x4(uint32_t* r, uint32_t addr) {
    asm volatile("ldmatrix.sync.aligned.m8n8.x4.shared.b16 {%0,%1,%2,%3}, [%4];"
        : "=r"(r[0]), "=r"(r[1]), "=r"(r[2]), "=r"(r[3]) : "r"(addr));
}

__device__ __forceinline__ void mma_bf16(float* d, const uint32_t* a, const uint32_t* b) {
    asm volatile("mma.sync.aligned.m16n8k16.row.col.f32.bf16.bf16.f32 "
        "{%0,%1,%2,%3}, {%4,%5,%6,%7}, {%8,%9}, {%0,%1,%2,%3};"
        : "+f"(d[0]), "+f"(d[1]), "+f"(d[2]), "+f"(d[3])
        : "r"(a[0]), "r"(a[1]), "r"(a[2]), "r"(a[3]), "r"(b[0]), "r"(b[1]));
}

__device__ __forceinline__ void cp16(uint32_t dst, const void* src) {
    asm volatile("cp.async.cg.shared.global [%0], [%1], 16;" :: "r"(dst), "l"(src));
}
#define CP_COMMIT() asm volatile("cp.async.commit_group;" ::: "memory")
#define CP_WAIT0()  asm volatile("cp.async.wait_group 0;" ::: "memory")

// ---------------------------------------------------------------------------
// Kernel 0: normalize memory rows -> bf16
// ---------------------------------------------------------------------------
__global__ void norm_mem_kernel(const float* __restrict__ mem) {
    int row = blockIdx.x;
    int t   = threadIdx.x;   // 128 threads, 4 floats each
    const float4* r = (const float4*)(mem + (size_t)row * C_);
    float4 v = r[t];
    float ss = v.x * v.x + v.y * v.y + v.z * v.z + v.w * v.w;
#pragma unroll
    for (int o = 16; o; o >>= 1) ss += __shfl_xor_sync(0xffffffffu, ss, o);
    __shared__ float ws[4];
    if ((t & 31) == 0) ws[t >> 5] = ss;
    __syncthreads();
    float tot = ws[0] + ws[1] + ws[2] + ws[3];
    float inv = 1.0f / fmaxf(sqrtf(tot), 1e-12f);
    __nv_bfloat162 p0 = __floats2bfloat162_rn(v.x * inv, v.y * inv);
    __nv_bfloat162 p1 = __floats2bfloat162_rn(v.z * inv, v.w * inv);
    uint2 o2;
    o2.x = *(uint32_t*)&p0;
    o2.y = *(uint32_t*)&p1;
    ((uint2*)(g_memn_bf + (size_t)row * C_))[t] = o2;
}

// ---------------------------------------------------------------------------
// Kernel 1: fused transpose+convert+norm.
// Block = 64 pixels (one hw tile) x ALL 512 channels, 256 threads.
// ---------------------------------------------------------------------------
__global__ __launch_bounds__(256) void xpose_norm_kernel(const float* __restrict__ x) {
    __shared__ float xs[64][65];
    int bid = blockIdx.x;
    int ht = bid & 63;            // hw tile (64 tiles of 64)
    int b  = bid >> 6;            // batch
    int t  = threadIdx.x;
    int hw = t & 63;
    int cl = t >> 6;              // 0..3
    int px = t >> 2;              // 0..63 (pixel within tile, write phase)
    int ch = (t & 3) * 16;        // 16-c chunk within 64-c tile

    float ss = 0.f;

    for (int ct = 0; ct < 8; ct++) {
        const float* src = x + ((size_t)b * C_ + ct * 64) * HW_ + ht * 64;
#pragma unroll
        for (int i = 0; i < 16; i++) {
            xs[cl + i * 4][hw] = src[(size_t)(cl + i * 4) * HW_ + hw];
        }
        __syncthreads();
        __nv_bfloat162 v[8];
#pragma unroll
        for (int j = 0; j < 8; j++) {
            float a = xs[ch + j * 2][px];
            float bb = xs[ch + j * 2 + 1][px];
            ss += a * a + bb * bb;
            v[j] = __floats2bfloat162_rn(a, bb);
        }
        size_t p = (size_t)b * HW_ + ht * 64 + px;
        uint4* dst = (uint4*)(g_xbf + p * C_ + ct * 64 + ch);
        dst[0] = *(uint4*)&v[0];
        dst[1] = *(uint4*)&v[4];
        __syncthreads();
    }

    ss += __shfl_xor_sync(0xffffffffu, ss, 1);
    ss += __shfl_xor_sync(0xffffffffu, ss, 2);
    if ((t & 3) == 0) {
        g_pnorm2[(size_t)b * HW_ + ht * 64 + px] = ss;
    }
}

// ---------------------------------------------------------------------------
// Kernel 2: bf16 HMMA GEMM + fused argmax, cp.async-pipelined B staging.
// CTA = 256 threads (8 warps) = 64 pixels; 2 CTAs/SM.
// A (64px x 512K bf16) SMEM-resident, pitch 520 bf16 (1040 B).
// Loop 8 N-tiles of 128 memory rows; B streamed in 64-K chunks, double-buffered
// via cp.async (no exposed LDG latency in the mainloop).
// ---------------------------------------------------------------------------
#define A_PITCH_B  1040          // 520 bf16
#define B_PITCH_B  144           // 72 bf16
#define OFF_B      66560         // 64 * 1040
#define B_CHUNK    18432         // 128 * 144
#define OFF_REDV   103424        // OFF_B + 2*B_CHUNK
#define OFF_REDI   104448
#define SMEM_BYTES 105472

__global__ __launch_bounds__(256, 2) void sim_mma_kernel() {
    extern __shared__ char smem[];
    uint32_t sb = smem_u32(smem);
    float* redv = (float*)(smem + OFF_REDV);   // [64][4]
    int*   redi = (int*)(smem + OFF_REDI);     // [64][4]

    int t    = threadIdx.x;
    int lane = t & 31;
    int w    = t >> 5;
    int wr   = w & 1;      // pixel half (32 px)
    int wc   = w >> 1;     // m quarter (32 m)
    int pix0 = blockIdx.x * 64;

    // B chunk loader via cp.async: rows nt*128..+127, k cols kc*64..+63
    auto loadB = [&](int nt, int kc, int buf) {
        const char* bsrc = (const char*)(g_memn_bf + (size_t)(nt * 128) * C_ + kc * 64);
        uint32_t bb = sb + OFF_B + (uint32_t)buf * B_CHUNK;
#pragma unroll
        for (int i = 0; i < 4; i++) {
            int idx = t + i * 256;           // 0..1023 quads (8 per row)
            int m = idx >> 3;
            int q = idx & 7;
            cp16(bb + (uint32_t)(m * B_PITCH_B + q * 16),
                 bsrc + (size_t)m * (C_ * 2) + q * 16);
        }
        CP_COMMIT();
    };

    // ---- prologue: A resident (cp.async) + first B chunk ----
    {
        const char* asrc = (const char*)(g_xbf + (size_t)pix0 * C_);
#pragma unroll
        for (int i = 0; i < 16; i++) {
            int idx = t + i * 256;           // 0..4095 (16B quads; 64 per row)
            int px = idx >> 6;
            int q  = idx & 63;
            cp16(sb + (uint32_t)(px * A_PITCH_B + q * 16),
                 asrc + (size_t)idx * 16);
        }
    }
    loadB(0, 0, 0);   // commits A quads + B chunk 0 as one group

    // ---- hoisted ldmatrix base addresses ----
    uint32_t aAddr[2];
#pragma unroll
    for (int i = 0; i < 2; i++)
        aAddr[i] = sb + (uint32_t)(wr * 32 + i * 16 + (lane & 15)) * A_PITCH_B
                      + (uint32_t)(lane >> 4) * 16u;
    uint32_t bAddr[2];
#pragma unroll
    for (int jp = 0; jp < 2; jp++)
        bAddr[jp] = sb + OFF_B
                  + (uint32_t)(wc * 32 + (2 * jp + (lane >> 4)) * 8 + (lane & 7)) * B_PITCH_B
                  + (uint32_t)((lane >> 3) & 1) * 16u;

    float bestv[2][2];
    int   besti[2][2];
#pragma unroll
    for (int i = 0; i < 2; i++) {
        bestv[i][0] = -1e30f; bestv[i][1] = -1e30f;
        besti[i][0] = 0;      besti[i][1] = 0;
    }

    for (int nt = 0; nt < 8; nt++) {
        float acc[2][4][4];
#pragma unroll
        for (int i = 0; i < 2; i++)
#pragma unroll
            for (int j = 0; j < 4; j++)
#pragma unroll
                for (int r = 0; r < 4; r++) acc[i][j][r] = 0.f;

        for (int kc = 0; kc < 8; kc++) {
            CP_WAIT0();        // chunk kc (and A on first iter) fully arrived
            __syncthreads();   // visible to all; compute(kc-1) done everywhere
            // issue next chunk into the other buffer (its readers are done)
            {
                int nkc = kc + 1, nnt = nt;
                if (nkc == 8) { nkc = 0; nnt = nt + 1; }
                if (nnt < 8) loadB(nnt, nkc, (kc + 1) & 1);
            }
            uint32_t bufOff = (uint32_t)((kc & 1) * B_CHUNK);
            uint32_t kcOff  = (uint32_t)(kc * 128);   // kc*64 bf16 cols in A
#pragma unroll
            for (int ks = 0; ks < 4; ks++) {
                uint32_t ko = (uint32_t)(ks * 32);    // 16 bf16 cols
                uint32_t af[2][4];
#pragma unroll
                for (int i = 0; i < 2; i++)
                    ldsm_x4(af[i], aAddr[i] + kcOff + ko);
                uint32_t bfr[2][4];
#pragma unroll
                for (int jp = 0; jp < 2; jp++)
                    ldsm_x4(bfr[jp], bAddr[jp] + bufOff + ko);
#pragma unroll
                for (int i = 0; i < 2; i++)
#pragma unroll
                    for (int j = 0; j < 4; j++)
                        mma_bf16(acc[i][j], af[i], &bfr[j >> 1][(j & 1) * 2]);
            }
        }

        // ---- fold this N-tile into running argmax (first-max tie-break) ----
#pragma unroll
        for (int i = 0; i < 2; i++)
#pragma unroll
            for (int rp = 0; rp < 2; rp++)
#pragma unroll
                for (int j = 0; j < 4; j++)
#pragma unroll
                    for (int c = 0; c < 2; c++) {
                        float v = acc[i][j][rp * 2 + c];
                        if (v > bestv[i][rp]) {
                            bestv[i][rp] = v;
                            besti[i][rp] = nt * 128 + wc * 32 + j * 8 + (lane & 3) * 2 + c;
                        }
                    }
    }

    // ---- quad reduction (cols within warp) + cross-warp smem reduction ----
#pragma unroll
    for (int i = 0; i < 2; i++)
#pragma unroll
        for (int rp = 0; rp < 2; rp++) {
            float v = bestv[i][rp];
            int   ix = besti[i][rp];
#pragma unroll
            for (int off = 1; off <= 2; off <<= 1) {
                float ov = __shfl_xor_sync(0xffffffffu, v, off);
                int   oi = __shfl_xor_sync(0xffffffffu, ix, off);
                if (ov > v || (ov == v && oi < ix)) { v = ov; ix = oi; }
            }
            if ((lane & 3) == 0) {
                int row = wr * 32 + i * 16 + (lane >> 2) + rp * 8;
                redv[row * 4 + wc] = v;
                redi[row * 4 + wc] = ix;
            }
        }
    __syncthreads();
    if (t < 64) {
        float bv = redv[t * 4];
        int   bi = redi[t * 4];
#pragma unroll
        for (int j = 1; j < 4; j++) {
            float v = redv[t * 4 + j];
            if (v > bv) { bv = v; bi = redi[t * 4 + j]; }
        }
        float n2 = g_pnorm2[pix0 + t];
        g_sel[pix0 + t] = (bv > THRESH * sqrtf(n2)) ? bi : -1;
    }
}

// ---------------------------------------------------------------------------
// Kernel 3: masked gather + channel-major scatter. float4 over hw.
// ---------------------------------------------------------------------------
__global__ void out_kernel(const float* __restrict__ mem, float* __restrict__ out) {
    int e4 = blockIdx.x * blockDim.x + threadIdx.x;
    int e  = e4 * 4;
    int hw = e & (HW_ - 1);
    int c  = (e >> 12) & (C_ - 1);
    int b  = e >> 21;
    int p  = b * HW_ + hw;
    int s0 = g_sel[p + 0];
    int s1 = g_sel[p + 1];
    int s2 = g_sel[p + 2];
    int s3 = g_sel[p + 3];
    float4 o;
    o.x = (s0 >= 0) ? mem[(size_t)s0 * C_ + c] : 0.f;
    o.y = (s1 >= 0) ? mem[(size_t)s1 * C_ + c] : 0.f;
    o.z = (s2 >= 0) ? mem[(size_t)s2 * C_ + c] : 0.f;
    o.w = (s3 >= 0) ? mem[(size_t)s3 * C_ + c] : 0.f;
    ((float4*)out)[e4] = o;
}

// ---------------------------------------------------------------------------
extern "C" void kernel_launch(void* const* d_in, const int* in_sizes, int n_in,
                              void* d_out, int out_size) {
    const float* x   = (const float*)d_in[0];   // 32*512*64*64
    const float* mem = (const float*)d_in[1];   // 1024*512
    float* out = (float*)d_out;

    cudaFuncSetAttribute(sim_mma_kernel,
                         cudaFuncAttributeMaxDynamicSharedMemorySize, SMEM_BYTES);

    norm_mem_kernel<<<M_, 128>>>(mem);
    xpose_norm_kernel<<<B_ * 64, 256>>>(x);
    sim_mma_kernel<<<NPIX / 64, 256, SMEM_BYTES>>>();
    out_kernel<<<(NPIX * C_ / 4) / 256, 256>>>(mem, out);
}

// round 10
// speedup vs baseline: 7.9085x; 1.1312x over previous
#include <cuda_runtime.h>
#include <cuda_bf16.h>
#include <cstdint>

// Problem constants
#define B_      32
#define C_      512
#define HW_     4096            // 64*64
#define NPIX    (B_ * HW_)      // 131072
#define M_      1024
#define THRESH  0.8f

// ---------------------------------------------------------------------------
// Device scratch (no cudaMalloc allowed)
// ---------------------------------------------------------------------------
__device__ __nv_bfloat16 g_memn_bf[M_ * C_];             // normalized memory, bf16

__device__ __forceinline__ uint32_t smem_u32(const void* p) {
    uint32_t a;
    asm("{ .reg .u64 t; cvta.to.shared.u64 t, %1; cvt.u32.u64 %0, t; }" : "=r"(a) : "l"(p));
    return a;
}

__device__ __forceinline__ void ldsm_x4(uint32_t* r, uint32_t addr) {
    asm volatile("ldmatrix.sync.aligned.m8n8.x4.shared.b16 {%0,%1,%2,%3}, [%4];"
        : "=r"(r[0]), "=r"(r[1]), "=r"(r[2]), "=r"(r[3]) : "r"(addr));
}

__device__ __forceinline__ void mma_bf16(float* d, const uint32_t* a, const uint32_t* b) {
    asm volatile("mma.sync.aligned.m16n8k16.row.col.f32.bf16.bf16.f32 "
        "{%0,%1,%2,%3}, {%4,%5,%6,%7}, {%8,%9}, {%0,%1,%2,%3};"
        : "+f"(d[0]), "+f"(d[1]), "+f"(d[2]), "+f"(d[3])
        : "r"(a[0]), "r"(a[1]), "r"(a[2]), "r"(a[3]), "r"(b[0]), "r"(b[1]));
}

__device__ __forceinline__ void cp16(uint32_t dst, const void* src) {
    asm volatile("cp.async.cg.shared.global [%0], [%1], 16;" :: "r"(dst), "l"(src));
}
#define CP_COMMIT() asm volatile("cp.async.commit_group;" ::: "memory")
#define CP_WAIT0()  asm volatile("cp.async.wait_group 0;" ::: "memory")

// ---------------------------------------------------------------------------
// Kernel 0: normalize memory rows -> bf16
// ---------------------------------------------------------------------------
__global__ void norm_mem_kernel(const float* __restrict__ mem) {
    int row = blockIdx.x;
    int t   = threadIdx.x;   // 128 threads, 4 floats each
    const float4* r = (const float4*)(mem + (size_t)row * C_);
    float4 v = r[t];
    float ss = v.x * v.x + v.y * v.y + v.z * v.z + v.w * v.w;
#pragma unroll
    for (int o = 16; o; o >>= 1) ss += __shfl_xor_sync(0xffffffffu, ss, o);
    __shared__ float ws[4];
    if ((t & 31) == 0) ws[t >> 5] = ss;
    __syncthreads();
    float tot = ws[0] + ws[1] + ws[2] + ws[3];
    float inv = 1.0f / fmaxf(sqrtf(tot), 1e-12f);
    __nv_bfloat162 p0 = __floats2bfloat162_rn(v.x * inv, v.y * inv);
    __nv_bfloat162 p1 = __floats2bfloat162_rn(v.z * inv, v.w * inv);
    uint2 o2;
    o2.x = *(uint32_t*)&p0;
    o2.y = *(uint32_t*)&p1;
    ((uint2*)(g_memn_bf + (size_t)row * C_))[t] = o2;
}

// ---------------------------------------------------------------------------
// Kernel 1: FULLY FUSED: transpose+convert+norm prologue, bf16 HMMA GEMM with
// cp.async-pipelined B staging, fused argmax, masked-gather output write.
// CTA = 256 threads (8 warps) = 64 pixels (one b, 64 consecutive hw); 2 CTAs/SM.
// ---------------------------------------------------------------------------
#define A_PITCH_B  1040          // 520 bf16
#define B_PITCH_B  144           // 72 bf16
#define OFF_B      66560         // 64 * 1040
#define B_CHUNK    18432         // 128 * 144
#define OFF_REDV   103424        // OFF_B + 2*B_CHUNK
#define OFF_REDI   104448
#define OFF_PN     105472        // 64 floats: per-pixel ||x||^2
#define OFF_SEL    105728        // 64 ints : selected row or -1
#define SMEM_BYTES 105984

__global__ __launch_bounds__(256, 2) void sim_fused_kernel(
    const float* __restrict__ x,
    const float* __restrict__ memf,
    float* __restrict__ out
) {
    extern __shared__ char smem[];
    uint32_t sb = smem_u32(smem);
    float* redv = (float*)(smem + OFF_REDV);   // [64][4]
    int*   redi = (int*)(smem + OFF_REDI);     // [64][4]
    float* pn   = (float*)(smem + OFF_PN);     // [64]
    int*   ssel = (int*)(smem + OFF_SEL);      // [64]

    int t    = threadIdx.x;
    int lane = t & 31;
    int w    = t >> 5;
    int wr   = w & 1;      // pixel half (32 px)
    int wc   = w >> 1;     // m quarter (32 m)
    int pix0 = blockIdx.x * 64;
    int b    = pix0 >> 12;            // pix0 / HW_
    int hw0  = pix0 & (HW_ - 1);

    // ================= PROLOGUE: x -> A tile (transpose+bf16+norm) =========
    {
        float* stage = (float*)(smem + OFF_B);   // [64][65] floats (16.6KB)
        int hwi = t & 63;
        int cl  = t >> 6;              // 0..3
        int px  = t >> 2;              // 0..63
        int ch  = (t & 3) * 16;        // 16-c slice within 64-c sub-tile
        float ss = 0.f;
        const float* xb = x + (size_t)b * C_ * HW_ + hw0;

        for (int ct = 0; ct < 8; ct++) {
            const float* src = xb + (size_t)(ct * 64) * HW_;
#pragma unroll
            for (int i = 0; i < 16; i++) {
                stage[(cl + i * 4) * 65 + hwi] = src[(size_t)(cl + i * 4) * HW_ + hwi];
            }
            __syncthreads();
            __nv_bfloat162 v[8];
#pragma unroll
            for (int j = 0; j < 8; j++) {
                float a  = stage[(ch + 2 * j) * 65 + px];
                float c2 = stage[(ch + 2 * j + 1) * 65 + px];
                ss += a * a + c2 * c2;
                v[j] = __floats2bfloat162_rn(a, c2);
            }
            uint4* dst = (uint4*)(smem + px * A_PITCH_B + (ct * 64 + ch) * 2);
            dst[0] = *(uint4*)&v[0];
            dst[1] = *(uint4*)&v[4];
            __syncthreads();
        }
        ss += __shfl_xor_sync(0xffffffffu, ss, 1);
        ss += __shfl_xor_sync(0xffffffffu, ss, 2);
        if ((t & 3) == 0) pn[px] = ss;
    }

    // ================= MAINLOOP: HMMA GEMM + argmax =========================
    // B chunk loader via cp.async: rows nt*128..+127, k cols kc*64..+63
    auto loadB = [&](int nt, int kc, int buf) {
        const char* bsrc = (const char*)(g_memn_bf + (size_t)(nt * 128) * C_ + kc * 64);
        uint32_t bbm = sb + OFF_B + (uint32_t)buf * B_CHUNK;
#pragma unroll
        for (int i = 0; i < 4; i++) {
            int idx = t + i * 256;           // 0..1023 quads (8 per row)
            int m = idx >> 3;
            int q = idx & 7;
            cp16(bbm + (uint32_t)(m * B_PITCH_B + q * 16),
                 bsrc + (size_t)m * (C_ * 2) + q * 16);
        }
        CP_COMMIT();
    };

    loadB(0, 0, 0);   // prologue B chunk

    uint32_t aAddr[2];
#pragma unroll
    for (int i = 0; i < 2; i++)
        aAddr[i] = sb + (uint32_t)(wr * 32 + i * 16 + (lane & 15)) * A_PITCH_B
                      + (uint32_t)(lane >> 4) * 16u;
    uint32_t bAddr[2];
#pragma unroll
    for (int jp = 0; jp < 2; jp++)
        bAddr[jp] = sb + OFF_B
                  + (uint32_t)(wc * 32 + (2 * jp + (lane >> 4)) * 8 + (lane & 7)) * B_PITCH_B
                  + (uint32_t)((lane >> 3) & 1) * 16u;

    float bestv[2][2];
    int   besti[2][2];
#pragma unroll
    for (int i = 0; i < 2; i++) {
        bestv[i][0] = -1e30f; bestv[i][1] = -1e30f;
        besti[i][0] = 0;      besti[i][1] = 0;
    }

    for (int nt = 0; nt < 8; nt++) {
        float acc[2][4][4];
#pragma unroll
        for (int i = 0; i < 2; i++)
#pragma unroll
            for (int j = 0; j < 4; j++)
#pragma unroll
                for (int r = 0; r < 4; r++) acc[i][j][r] = 0.f;

        for (int kc = 0; kc < 8; kc++) {
            CP_WAIT0();        // chunk kc arrived
            __syncthreads();   // visible everywhere; compute(kc-1) done
            {
                int nkc = kc + 1, nnt = nt;
                if (nkc == 8) { nkc = 0; nnt = nt + 1; }
                if (nnt < 8) loadB(nnt, nkc, (kc + 1) & 1);
            }
            uint32_t bufOff = (uint32_t)((kc & 1) * B_CHUNK);
            uint32_t kcOff  = (uint32_t)(kc * 128);   // kc*64 bf16 cols in A
#pragma unroll
            for (int ks = 0; ks < 4; ks++) {
                uint32_t ko = (uint32_t)(ks * 32);    // 16 bf16 cols
                uint32_t af[2][4];
#pragma unroll
                for (int i = 0; i < 2; i++)
                    ldsm_x4(af[i], aAddr[i] + kcOff + ko);
                uint32_t bfr[2][4];
#pragma unroll
                for (int jp = 0; jp < 2; jp++)
                    ldsm_x4(bfr[jp], bAddr[jp] + bufOff + ko);
#pragma unroll
                for (int i = 0; i < 2; i++)
#pragma unroll
                    for (int j = 0; j < 4; j++)
                        mma_bf16(acc[i][j], af[i], &bfr[j >> 1][(j & 1) * 2]);
            }
        }

        // fold N-tile into running argmax (first-max tie-break)
#pragma unroll
        for (int i = 0; i < 2; i++)
#pragma unroll
            for (int rp = 0; rp < 2; rp++)
#pragma unroll
                for (int j = 0; j < 4; j++)
#pragma unroll
                    for (int c = 0; c < 2; c++) {
                        float v = acc[i][j][rp * 2 + c];
                        if (v > bestv[i][rp]) {
                            bestv[i][rp] = v;
                            besti[i][rp] = nt * 128 + wc * 32 + j * 8 + (lane & 3) * 2 + c;
                        }
                    }
    }

    // ================= EPILOGUE: reductions + selection =====================
#pragma unroll
    for (int i = 0; i < 2; i++)
#pragma unroll
        for (int rp = 0; rp < 2; rp++) {
            float v = bestv[i][rp];
            int   ix = besti[i][rp];
#pragma unroll
            for (int off = 1; off <= 2; off <<= 1) {
                float ov = __shfl_xor_sync(0xffffffffu, v, off);
                int   oi = __shfl_xor_sync(0xffffffffu, ix, off);
                if (ov > v || (ov == v && oi < ix)) { v = ov; ix = oi; }
            }
            if ((lane & 3) == 0) {
                int row = wr * 32 + i * 16 + (lane >> 2) + rp * 8;
                redv[row * 4 + wc] = v;
                redi[row * 4 + wc] = ix;
            }
        }
    __syncthreads();
    if (t < 64) {
        float bv = redv[t * 4];
        int   bi = redi[t * 4];
#pragma unroll
        for (int j = 1; j < 4; j++) {
            float v = redv[t * 4 + j];
            if (v > bv) { bv = v; bi = redi[t * 4 + j]; }
        }
        float n2 = pn[t];
        ssel[t] = (bv > THRESH * sqrtf(n2)) ? bi : -1;
    }
    __syncthreads();

    // ================= OUTPUT: masked gather, channel-major write ===========
    {
        int pxo = (t & 31) * 2;          // pixel pair
        int c0  = t >> 5;                // 0..7
        int s0 = ssel[pxo];
        int s1 = ssel[pxo + 1];
        const float* mr0 = memf + (size_t)(s0 < 0 ? 0 : s0) * C_;
        const float* mr1 = memf + (size_t)(s1 < 0 ? 0 : s1) * C_;
        float* ob = out + ((size_t)b * C_) * HW_ + hw0 + pxo;
#pragma unroll 8
        for (int i = 0; i < 64; i++) {
            int c = c0 + i * 8;
            float2 v;
            v.x = (s0 >= 0) ? mr0[c] : 0.f;
            v.y = (s1 >= 0) ? mr1[c] : 0.f;
            *(float2*)(ob + (size_t)c * HW_) = v;
        }
    }
}

// ---------------------------------------------------------------------------
extern "C" void kernel_launch(void* const* d_in, const int* in_sizes, int n_in,
                              void* d_out, int out_size) {
    const float* x   = (const float*)d_in[0];   // 32*512*64*64
    const float* mem = (const float*)d_in[1];   // 1024*512
    float* out = (float*)d_out;

    cudaFuncSetAttribute(sim_fused_kernel,
                         cudaFuncAttributeMaxDynamicSharedMemorySize, SMEM_BYTES);

    norm_mem_kernel<<<M_, 128>>>(mem);
    sim_fused_kernel<<<NPIX / 64, 256, SMEM_BYTES>>>(x, mem, out);
}

// round 11
// speedup vs baseline: 8.0219x; 1.0143x over previous
#include <cuda_runtime.h>
#include <cuda_bf16.h>
#include <cstdint>

// Problem constants
#define B_      32
#define C_      512
#define HW_     4096            // 64*64
#define NPIX    (B_ * HW_)      // 131072
#define M_      1024
#define THRESH  0.8f
#define MSCALE  16.0f           // fp8 scale applied to normalized memory rows

// ---------------------------------------------------------------------------
// Device scratch (no cudaMalloc allowed)
// ---------------------------------------------------------------------------
__device__ uint8_t g_mem8[M_ * C_];     // normalized memory * 16, e4m3

__device__ __forceinline__ uint32_t smem_u32(const void* p) {
    uint32_t a;
    asm("{ .reg .u64 t; cvta.to.shared.u64 t, %1; cvt.u32.u64 %0, t; }" : "=r"(a) : "l"(p));
    return a;
}

__device__ __forceinline__ void ldsm_x4(uint32_t* r, uint32_t addr) {
    asm volatile("ldmatrix.sync.aligned.m8n8.x4.shared.b16 {%0,%1,%2,%3}, [%4];"
        : "=r"(r[0]), "=r"(r[1]), "=r"(r[2]), "=r"(r[3]) : "r"(addr));
}

__device__ __forceinline__ void mma_fp8(float* d, const uint32_t* a, const uint32_t* b) {
    asm volatile("mma.sync.aligned.m16n8k32.row.col.f32.e4m3.e4m3.f32 "
        "{%0,%1,%2,%3}, {%4,%5,%6,%7}, {%8,%9}, {%0,%1,%2,%3};"
        : "+f"(d[0]), "+f"(d[1]), "+f"(d[2]), "+f"(d[3])
        : "r"(a[0]), "r"(a[1]), "r"(a[2]), "r"(a[3]), "r"(b[0]), "r"(b[1]));
}

// pack 2 floats -> 2 e4m3 bytes. Used identically for x and memory, so the
// lo/hi convention is a consistent k-permutation (dot-invariant).
__device__ __forceinline__ uint16_t pk2(float lo, float hi) {
    uint16_t r;
    asm("cvt.rn.satfinite.e4m3x2.f32 %0, %1, %2;" : "=h"(r) : "f"(hi), "f"(lo));
    return r;
}

__device__ __forceinline__ void cp16(uint32_t dst, const void* src) {
    asm volatile("cp.async.cg.shared.global [%0], [%1], 16;" :: "r"(dst), "l"(src));
}
#define CP_COMMIT() asm volatile("cp.async.commit_group;" ::: "memory")
#define CP_WAIT0()  asm volatile("cp.async.wait_group 0;" ::: "memory")

// ---------------------------------------------------------------------------
// Kernel 0: normalize memory rows -> e4m3 (scaled by 16)
// ---------------------------------------------------------------------------
__global__ void norm_mem_kernel(const float* __restrict__ mem) {
    int row = blockIdx.x;
    int t   = threadIdx.x;   // 128 threads, 4 floats each
    const float4* r = (const float4*)(mem + (size_t)row * C_);
    float4 v = r[t];
    float ss = v.x * v.x + v.y * v.y + v.z * v.z + v.w * v.w;
#pragma unroll
    for (int o = 16; o; o >>= 1) ss += __shfl_xor_sync(0xffffffffu, ss, o);
    __shared__ float ws[4];
    if ((t & 31) == 0) ws[t >> 5] = ss;
    __syncthreads();
    float tot = ws[0] + ws[1] + ws[2] + ws[3];
    float inv = MSCALE / fmaxf(sqrtf(tot), 1e-12f);
    uint16_t a = pk2(v.x * inv, v.y * inv);
    uint16_t b = pk2(v.z * inv, v.w * inv);
    ((uint32_t*)(g_mem8 + (size_t)row * C_))[t] = (uint32_t)a | ((uint32_t)b << 16);
}

// ---------------------------------------------------------------------------
// Kernel 1: FULLY FUSED fp8 pipeline.
// CTA = 256 threads (8 warps) = 128 pixels (one b, 128 consecutive hw); 2/SM.
// A (128px x 512K e4m3) SMEM-resident, pitch 528 B (33 quads -> conflict-free
// ldmatrix). Loop 8 N-tiles of 128 memory rows; B streamed in 64-K fp8 chunks
// (pitch 80 B), double-buffered via cp.async. Warp tile 64px x 32m:
// per 32-k step: 4+2 LDSM.x4 -> 16 QMMA. Fused argmax + masked output write.
// ---------------------------------------------------------------------------
#define A_PITCH    528
#define B_PITCH    80
#define OFF_B      67584         // 128 * 528
#define B_CHUNK    10240         // 128 * 80
#define OFF_REDV   88064         // OFF_B + 2*B_CHUNK
#define OFF_REDI   90112
#define OFF_PN     92160         // 128 floats
#define OFF_SEL    92672         // 128 ints
#define SMEM_BYTES 93184

__global__ __launch_bounds__(256, 2) void sim_fused_kernel(
    const float* __restrict__ x,
    const float* __restrict__ memf,
    float* __restrict__ out
) {
    extern __shared__ char smem[];
    uint32_t sb = smem_u32(smem);
    float* redv = (float*)(smem + OFF_REDV);   // [128][4]
    int*   redi = (int*)(smem + OFF_REDI);     // [128][4]
    float* pn   = (float*)(smem + OFF_PN);     // [128]
    int*   ssel = (int*)(smem + OFF_SEL);      // [128]

    int t    = threadIdx.x;
    int lane = t & 31;
    int w    = t >> 5;
    int wr   = w & 1;      // pixel half (64 px)
    int wc   = w >> 1;     // m quarter (32 m)
    int pix0 = blockIdx.x * 128;
    int b    = pix0 >> 12;
    int hw0  = pix0 & (HW_ - 1);

    // B chunk loader via cp.async: rows nt*128..+127, k bytes kc*64..+63
    auto loadB = [&](int nt, int kc, int buf) {
        const char* bsrc = (const char*)g_mem8 + (size_t)(nt * 128) * C_ + kc * 64;
        uint32_t bbm = sb + OFF_B + (uint32_t)buf * B_CHUNK;
#pragma unroll
        for (int i = 0; i < 2; i++) {
            int idx = t + i * 256;           // 0..511 quads (4 per row)
            int m = idx >> 2;
            int q = idx & 3;
            cp16(bbm + (uint32_t)(m * B_PITCH + q * 16),
                 bsrc + (size_t)m * C_ + q * 16);
        }
        CP_COMMIT();
    };

    // ---- preload B chunk 0 into buf0 (overlaps the whole prologue) ----
    loadB(0, 0, 0);

    // ================= PROLOGUE: x -> A tile (transpose + e4m3 + norm) =====
    {
        float* stage = (float*)(smem + OFF_B + B_CHUNK);   // buf1: 16x129 floats
        int hwi = t & 127;
        int cg  = t >> 7;              // 0..1
        int px  = t >> 1;              // 0..127
        int sl  = t & 1;               // 8-channel slice within 16-c sub-tile
        float ss = 0.f;
        const float* xb = x + (size_t)b * C_ * HW_ + hw0;

        for (int ct = 0; ct < 32; ct++) {     // 16 channels per iteration
            const float* src = xb + (size_t)(ct * 16) * HW_;
#pragma unroll
            for (int i = 0; i < 8; i++) {
                stage[(cg + i * 2) * 129 + hwi] = src[(size_t)(cg + i * 2) * HW_ + hwi];
            }
            __syncthreads();
            uint16_t h4[4];
#pragma unroll
            for (int j = 0; j < 4; j++) {
                float a  = stage[(sl * 8 + 2 * j) * 129 + px];
                float c2 = stage[(sl * 8 + 2 * j + 1) * 129 + px];
                ss += a * a + c2 * c2;
                h4[j] = pk2(a, c2);
            }
            uint2 r2;
            r2.x = (uint32_t)h4[0] | ((uint32_t)h4[1] << 16);
            r2.y = (uint32_t)h4[2] | ((uint32_t)h4[3] << 16);
            *(uint2*)(smem + px * A_PITCH + ct * 16 + sl * 8) = r2;
            __syncthreads();
        }
        ss += __shfl_xor_sync(0xffffffffu, ss, 1);
        if (sl == 0) pn[px] = ss;
    }

    // ================= MAINLOOP: fp8 QMMA GEMM + argmax =====================
    uint32_t aAddr[4];
#pragma unroll
    for (int i = 0; i < 4; i++)
        aAddr[i] = sb + (uint32_t)(wr * 64 + i * 16 + (lane & 15)) * A_PITCH
                      + (uint32_t)(lane >> 4) * 16u;
    uint32_t bAddr[2];
#pragma unroll
    for (int jp = 0; jp < 2; jp++)
        bAddr[jp] = sb + OFF_B
                  + (uint32_t)(wc * 32 + (2 * jp + (lane >> 4)) * 8 + (lane & 7)) * B_PITCH
                  + (uint32_t)((lane >> 3) & 1) * 16u;

    float bestv[4][2];
    int   besti[4][2];
#pragma unroll
    for (int i = 0; i < 4; i++) {
        bestv[i][0] = -1e30f; bestv[i][1] = -1e30f;
        besti[i][0] = 0;      besti[i][1] = 0;
    }

    for (int nt = 0; nt < 8; nt++) {
        float acc[4][4][4];
#pragma unroll
        for (int i = 0; i < 4; i++)
#pragma unroll
            for (int j = 0; j < 4; j++)
#pragma unroll
                for (int r = 0; r < 4; r++) acc[i][j][r] = 0.f;

        for (int kc = 0; kc < 8; kc++) {
            CP_WAIT0();        // chunk kc fully arrived
            __syncthreads();   // visible everywhere; compute(kc-1) done
            {
                int nkc = kc + 1, nnt = nt;
                if (nkc == 8) { nkc = 0; nnt = nt + 1; }
                if (nnt < 8) loadB(nnt, nkc, (kc + 1) & 1);
            }
            uint32_t bufOff = (uint32_t)((kc & 1) * B_CHUNK);
            uint32_t kcOff  = (uint32_t)(kc * 64);    // 64 fp8 bytes per chunk
#pragma unroll
            for (int ks = 0; ks < 2; ks++) {
                uint32_t ko = (uint32_t)(ks * 32);    // 32 fp8 = one k32 step
                uint32_t af[4][4];
#pragma unroll
                for (int i = 0; i < 4; i++)
                    ldsm_x4(af[i], aAddr[i] + kcOff + ko);
                uint32_t bfr[2][4];
#pragma unroll
                for (int jp = 0; jp < 2; jp++)
                    ldsm_x4(bfr[jp], bAddr[jp] + bufOff + ko);
#pragma unroll
                for (int i = 0; i < 4; i++)
#pragma unroll
                    for (int j = 0; j < 4; j++)
                        mma_fp8(acc[i][j], af[i], &bfr[j >> 1][(j & 1) * 2]);
            }
        }

        // fold N-tile into running argmax (first-max tie-break)
#pragma unroll
        for (int i = 0; i < 4; i++)
#pragma unroll
            for (int rp = 0; rp < 2; rp++)
#pragma unroll
                for (int j = 0; j < 4; j++)
#pragma unroll
                    for (int c = 0; c < 2; c++) {
                        float v = acc[i][j][rp * 2 + c];
                        if (v > bestv[i][rp]) {
                            bestv[i][rp] = v;
                            besti[i][rp] = nt * 128 + wc * 32 + j * 8 + (lane & 3) * 2 + c;
                        }
                    }
    }

    // ================= EPILOGUE: reductions + selection =====================
#pragma unroll
    for (int i = 0; i < 4; i++)
#pragma unroll
        for (int rp = 0; rp < 2; rp++) {
            float v = bestv[i][rp];
            int   ix = besti[i][rp];
#pragma unroll
            for (int off = 1; off <= 2; off <<= 1) {
                float ov = __shfl_xor_sync(0xffffffffu, v, off);
                int   oi = __shfl_xor_sync(0xffffffffu, ix, off);
                if (ov > v || (ov == v && oi < ix)) { v = ov; ix = oi; }
            }
            if ((lane & 3) == 0) {
                int row = wr * 64 + i * 16 + (lane >> 2) + rp * 8;
                redv[row * 4 + wc] = v;
                redi[row * 4 + wc] = ix;
            }
        }
    __syncthreads();
    if (t < 128) {
        float bv = redv[t * 4];
        int   bi = redi[t * 4];
#pragma unroll
        for (int j = 1; j < 4; j++) {
            float v = redv[t * 4 + j];
            if (v > bv) { bv = v; bi = redi[t * 4 + j]; }
        }
        float n2 = pn[t];
        // dot_q ~ 16 * (x . m_hat); fire iff dot_q > 0.8 * 16 * ||x||
        ssel[t] = (bv > (THRESH * MSCALE) * sqrtf(n2)) ? bi : -1;
    }
    __syncthreads();

    // ================= OUTPUT: masked gather, channel-major write ===========
    {
        int pxo = (t & 63) * 2;          // pixel pair
        int c0  = t >> 6;                // 0..3
        int s0 = ssel[pxo];
        int s1 = ssel[pxo + 1];
        const float* mr0 = memf + (size_t)(s0 < 0 ? 0 : s0) * C_;
        const float* mr1 = memf + (size_t)(s1 < 0 ? 0 : s1) * C_;
        float* ob = out + ((size_t)b * C_) * HW_ + hw0 + pxo;
#pragma unroll 8
        for (int i = 0; i < 128; i++) {
            int c = c0 + i * 4;
            float2 v;
            v.x = (s0 >= 0) ? mr0[c] : 0.f;
            v.y = (s1 >= 0) ? mr1[c] : 0.f;
            *(float2*)(ob + (size_t)c * HW_) = v;
        }
    }
}

// ---------------------------------------------------------------------------
extern "C" void kernel_launch(void* const* d_in, const int* in_sizes, int n_in,
                              void* d_out, int out_size) {
    const float* x   = (const float*)d_in[0];   // 32*512*64*64
    const float* mem = (const float*)d_in[1];   // 1024*512
    float* out = (float*)d_out;

    cudaFuncSetAttribute(sim_fused_kernel,
                         cudaFuncAttributeMaxDynamicSharedMemorySize, SMEM_BYTES);

    norm_mem_kernel<<<M_, 128>>>(mem);
    sim_fused_kernel<<<NPIX / 128, 256, SMEM_BYTES>>>(x, mem, out);
}

// round 12
// speedup vs baseline: 8.8316x; 1.1009x over previous
#include <cuda_runtime.h>
#include <cuda_bf16.h>
#include <cstdint>

// Problem constants
#define B_      32
#define C_      512
#define HW_     4096            // 64*64
#define NPIX    (B_ * HW_)      // 131072
#define M_      1024
#define THRESH  0.8f
#define MSCALE  16.0f           // fp8 scale applied to normalized memory rows

// ---------------------------------------------------------------------------
// Device scratch (no cudaMalloc allowed)
// ---------------------------------------------------------------------------
__device__ uint8_t g_mem8[M_ * C_];     // normalized memory * 16, e4m3

__device__ __forceinline__ uint32_t smem_u32(const void* p) {
    uint32_t a;
    asm("{ .reg .u64 t; cvta.to.shared.u64 t, %1; cvt.u32.u64 %0, t; }" : "=r"(a) : "l"(p));
    return a;
}

__device__ __forceinline__ void ldsm_x4(uint32_t* r, uint32_t addr) {
    asm volatile("ldmatrix.sync.aligned.m8n8.x4.shared.b16 {%0,%1,%2,%3}, [%4];"
        : "=r"(r[0]), "=r"(r[1]), "=r"(r[2]), "=r"(r[3]) : "r"(addr));
}

__device__ __forceinline__ void mma_fp8(float* d, const uint32_t* a, const uint32_t* b) {
    asm volatile("mma.sync.aligned.m16n8k32.row.col.f32.e4m3.e4m3.f32 "
        "{%0,%1,%2,%3}, {%4,%5,%6,%7}, {%8,%9}, {%0,%1,%2,%3};"
        : "+f"(d[0]), "+f"(d[1]), "+f"(d[2]), "+f"(d[3])
        : "r"(a[0]), "r"(a[1]), "r"(a[2]), "r"(a[3]), "r"(b[0]), "r"(b[1]));
}

// pack 2 floats -> 2 e4m3 bytes (same helper for x and memory: consistent
// k-permutation, dot-invariant).
__device__ __forceinline__ uint16_t pk2(float lo, float hi) {
    uint16_t r;
    asm("cvt.rn.satfinite.e4m3x2.f32 %0, %1, %2;" : "=h"(r) : "f"(hi), "f"(lo));
    return r;
}

__device__ __forceinline__ void cp16(uint32_t dst, const void* src) {
    asm volatile("cp.async.cg.shared.global [%0], [%1], 16;" :: "r"(dst), "l"(src));
}
#define CP_COMMIT() asm volatile("cp.async.commit_group;" ::: "memory")
#define CP_WAIT0()  asm volatile("cp.async.wait_group 0;" ::: "memory")

// ---------------------------------------------------------------------------
// Kernel 0: normalize memory rows -> e4m3 (scaled by 16)
// ---------------------------------------------------------------------------
__global__ void norm_mem_kernel(const float* __restrict__ mem) {
    int row = blockIdx.x;
    int t   = threadIdx.x;   // 128 threads, 4 floats each
    const float4* r = (const float4*)(mem + (size_t)row * C_);
    float4 v = r[t];
    float ss = v.x * v.x + v.y * v.y + v.z * v.z + v.w * v.w;
#pragma unroll
    for (int o = 16; o; o >>= 1) ss += __shfl_xor_sync(0xffffffffu, ss, o);
    __shared__ float ws[4];
    if ((t & 31) == 0) ws[t >> 5] = ss;
    __syncthreads();
    float tot = ws[0] + ws[1] + ws[2] + ws[3];
    float inv = MSCALE / fmaxf(sqrtf(tot), 1e-12f);
    uint16_t a = pk2(v.x * inv, v.y * inv);
    uint16_t b = pk2(v.z * inv, v.w * inv);
    ((uint32_t*)(g_mem8 + (size_t)row * C_))[t] = (uint32_t)a | ((uint32_t)b << 16);
}

// ---------------------------------------------------------------------------
// Kernel 1: FULLY FUSED fp8 pipeline, 3 CTAs/SM.
// CTA = 256 threads (8 warps) = 64 pixels (one b, 64 consecutive hw).
// A (64px x 512K e4m3) SMEM-resident, pitch 528 B. Loop 8 N-tiles of 128
// memory rows; B streamed in 128-K fp8 chunks (128 rows x 128 B, pitch 144),
// double-buffered via cp.async. Warp tile 32px x 32m: per k32 step
// 2+2 LDSM.x4 -> 8 QMMA. Fused argmax + masked channel-major output write.
// ---------------------------------------------------------------------------
#define A_PITCH    528
#define B_PITCH    144
#define OFF_B      33792         // 64 * 528
#define B_CHUNK    18432         // 128 * 144
#define OFF_REDV   70656         // OFF_B + 2*B_CHUNK
#define OFF_REDI   71680
#define OFF_PN     72704         // 64 floats
#define OFF_SEL    72960         // 64 ints
#define SMEM_BYTES 73216

__global__ __launch_bounds__(256, 3) void sim_fused_kernel(
    const float* __restrict__ x,
    const float* __restrict__ memf,
    float* __restrict__ out
) {
    extern __shared__ char smem[];
    uint32_t sb = smem_u32(smem);
    float* redv = (float*)(smem + OFF_REDV);   // [64][4]
    int*   redi = (int*)(smem + OFF_REDI);     // [64][4]
    float* pn   = (float*)(smem + OFF_PN);     // [64]
    int*   ssel = (int*)(smem + OFF_SEL);      // [64]

    int t    = threadIdx.x;
    int lane = t & 31;
    int w    = t >> 5;
    int wr   = w & 1;      // pixel half (32 px)
    int wc   = w >> 1;     // m quarter (32 m)
    int pix0 = blockIdx.x * 64;
    int b    = pix0 >> 12;
    int hw0  = pix0 & (HW_ - 1);

    // B chunk loader via cp.async: rows nt*128..+127, k bytes kc*128..+127
    auto loadB = [&](int nt, int kc, int buf) {
        const char* bsrc = (const char*)g_mem8 + (size_t)(nt * 128) * C_ + kc * 128;
        uint32_t bbm = sb + OFF_B + (uint32_t)buf * B_CHUNK;
#pragma unroll
        for (int i = 0; i < 4; i++) {
            int idx = t + i * 256;           // 0..1023 quads (8 per row)
            int m = idx >> 3;
            int q = idx & 7;
            cp16(bbm + (uint32_t)(m * B_PITCH + q * 16),
                 bsrc + (size_t)m * C_ + q * 16);
        }
        CP_COMMIT();
    };

    // ---- preload B chunk 0 into buf0 (overlaps the whole prologue) ----
    loadB(0, 0, 0);

    // ================= PROLOGUE: x -> A tile (transpose + e4m3 + norm) =====
    // Staging buffer lives in B buf1 (18.4KB >= 64*65*4 = 16.6KB).
    {
        float* stage = (float*)(smem + OFF_B + B_CHUNK);   // [64][65] floats
        int hwi = t & 63;
        int cl  = t >> 6;              // 0..3
        int px  = t >> 2;              // 0..63
        int ch  = (t & 3) * 16;        // 16-c slice within 64-c sub-tile
        float ss = 0.f;
        const float* xb = x + (size_t)b * C_ * HW_ + hw0;

        for (int ct = 0; ct < 8; ct++) {
            const float* src = xb + (size_t)(ct * 64) * HW_;
#pragma unroll
            for (int i = 0; i < 16; i++) {
                stage[(cl + i * 4) * 65 + hwi] = src[(size_t)(cl + i * 4) * HW_ + hwi];
            }
            __syncthreads();
            uint16_t h8[8];
#pragma unroll
            for (int j = 0; j < 8; j++) {
                float a  = stage[(ch + 2 * j) * 65 + px];
                float c2 = stage[(ch + 2 * j + 1) * 65 + px];
                ss += a * a + c2 * c2;
                h8[j] = pk2(a, c2);
            }
            uint4 r4;
            r4.x = (uint32_t)h8[0] | ((uint32_t)h8[1] << 16);
            r4.y = (uint32_t)h8[2] | ((uint32_t)h8[3] << 16);
            r4.z = (uint32_t)h8[4] | ((uint32_t)h8[5] << 16);
            r4.w = (uint32_t)h8[6] | ((uint32_t)h8[7] << 16);
            *(uint4*)(smem + px * A_PITCH + ct * 64 + ch) = r4;
            __syncthreads();
        }
        ss += __shfl_xor_sync(0xffffffffu, ss, 1);
        ss += __shfl_xor_sync(0xffffffffu, ss, 2);
        if ((t & 3) == 0) pn[px] = ss;
    }

    // ================= MAINLOOP: fp8 QMMA GEMM + argmax =====================
    uint32_t aAddr[2];
#pragma unroll
    for (int i = 0; i < 2; i++)
        aAddr[i] = sb + (uint32_t)(wr * 32 + i * 16 + (lane & 15)) * A_PITCH
                      + (uint32_t)(lane >> 4) * 16u;
    uint32_t bAddr[2];
#pragma unroll
    for (int jp = 0; jp < 2; jp++)
        bAddr[jp] = sb + OFF_B
                  + (uint32_t)(wc * 32 + (2 * jp + (lane >> 4)) * 8 + (lane & 7)) * B_PITCH
                  + (uint32_t)((lane >> 3) & 1) * 16u;

    float bestv[2][2];
    int   besti[2][2];
#pragma unroll
    for (int i = 0; i < 2; i++) {
        bestv[i][0] = -1e30f; bestv[i][1] = -1e30f;
        besti[i][0] = 0;      besti[i][1] = 0;
    }

    for (int nt = 0; nt < 8; nt++) {
        float acc[2][4][4];
#pragma unroll
        for (int i = 0; i < 2; i++)
#pragma unroll
            for (int j = 0; j < 4; j++)
#pragma unroll
                for (int r = 0; r < 4; r++) acc[i][j][r] = 0.f;

        for (int kc = 0; kc < 4; kc++) {          // 4 chunks of k=128
            CP_WAIT0();        // chunk kc fully arrived
            __syncthreads();   // visible everywhere; compute(kc-1) done
            {
                int nkc = kc + 1, nnt = nt;
                if (nkc == 4) { nkc = 0; nnt = nt + 1; }
                if (nnt < 8) loadB(nnt, nkc, (kc + 1) & 1);
            }
            uint32_t bufOff = (uint32_t)((kc & 1) * B_CHUNK);
            uint32_t kcOff  = (uint32_t)(kc * 128);   // 128 fp8 bytes per chunk
#pragma unroll
            for (int ks = 0; ks < 4; ks++) {
                uint32_t ko = (uint32_t)(ks * 32);    // 32 fp8 = one k32 step
                uint32_t af[2][4];
#pragma unroll
                for (int i = 0; i < 2; i++)
                    ldsm_x4(af[i], aAddr[i] + kcOff + ko);
                uint32_t bfr[2][4];
#pragma unroll
                for (int jp = 0; jp < 2; jp++)
                    ldsm_x4(bfr[jp], bAddr[jp] + bufOff + ko);
#pragma unroll
                for (int i = 0; i < 2; i++)
#pragma unroll
                    for (int j = 0; j < 4; j++)
                        mma_fp8(acc[i][j], af[i], &bfr[j >> 1][(j & 1) * 2]);
            }
        }

        // fold N-tile into running argmax (first-max tie-break)
#pragma unroll
        for (int i = 0; i < 2; i++)
#pragma unroll
            for (int rp = 0; rp < 2; rp++)
#pragma unroll
                for (int j = 0; j < 4; j++)
#pragma unroll
                    for (int c = 0; c < 2; c++) {
                        float v = acc[i][j][rp * 2 + c];
                        if (v > bestv[i][rp]) {
                            bestv[i][rp] = v;
                            besti[i][rp] = nt * 128 + wc * 32 + j * 8 + (lane & 3) * 2 + c;
                        }
                    }
    }

    // ================= EPILOGUE: reductions + selection =====================
#pragma unroll
    for (int i = 0; i < 2; i++)
#pragma unroll
        for (int rp = 0; rp < 2; rp++) {
            float v = bestv[i][rp];
            int   ix = besti[i][rp];
#pragma unroll
            for (int off = 1; off <= 2; off <<= 1) {
                float ov = __shfl_xor_sync(0xffffffffu, v, off);
                int   oi = __shfl_xor_sync(0xffffffffu, ix, off);
                if (ov > v || (ov == v && oi < ix)) { v = ov; ix = oi; }
            }
            if ((lane & 3) == 0) {
                int row = wr * 32 + i * 16 + (lane >> 2) + rp * 8;
                redv[row * 4 + wc] = v;
                redi[row * 4 + wc] = ix;
            }
        }
    __syncthreads();
    if (t < 64) {
        float bv = redv[t * 4];
        int   bi = redi[t * 4];
#pragma unroll
        for (int j = 1; j < 4; j++) {
            float v = redv[t * 4 + j];
            if (v > bv) { bv = v; bi = redi[t * 4 + j]; }
        }
        float n2 = pn[t];
        // dot_q ~ 16 * (x . m_hat); fire iff dot_q > 0.8 * 16 * ||x||
        ssel[t] = (bv > (THRESH * MSCALE) * sqrtf(n2)) ? bi : -1;
    }
    __syncthreads();

    // ================= OUTPUT: masked gather, channel-major write ===========
    {
        int pxo = (t & 31) * 2;          // pixel pair
        int c0  = t >> 5;                // 0..7
        int s0 = ssel[pxo];
        int s1 = ssel[pxo + 1];
        const float* mr0 = memf + (size_t)(s0 < 0 ? 0 : s0) * C_;
        const float* mr1 = memf + (size_t)(s1 < 0 ? 0 : s1) * C_;
        float* ob = out + ((size_t)b * C_) * HW_ + hw0 + pxo;
#pragma unroll 8
        for (int i = 0; i < 64; i++) {
            int c = c0 + i * 8;
            float2 v;
            v.x = (s0 >= 0) ? mr0[c] : 0.f;
            v.y = (s1 >= 0) ? mr1[c] : 0.f;
            *(float2*)(ob + (size_t)c * HW_) = v;
        }
    }
}

// ---------------------------------------------------------------------------
extern "C" void kernel_launch(void* const* d_in, const int* in_sizes, int n_in,
                              void* d_out, int out_size) {
    const float* x   = (const float*)d_in[0];   // 32*512*64*64
    const float* mem = (const float*)d_in[1];   // 1024*512
    float* out = (float*)d_out;

    cudaFuncSetAttribute(sim_fused_kernel,
                         cudaFuncAttributeMaxDynamicSharedMemorySize, SMEM_BYTES);

    norm_mem_kernel<<<M_, 128>>>(mem);
    sim_fused_kernel<<<NPIX / 64, 256, SMEM_BYTES>>>(x, mem, out);
}